// round 1
// baseline (speedup 1.0000x reference)
#include <cuda_runtime.h>
#include <cuda_bf16.h>
#include <math.h>

// Problem dims
#define Bv 128
#define Tv 1024
#define Iv 512
#define Hv 1024
#define Ov 256

#define NBLK_SCAN 128   // 16 k-chunks x 8 n-tiles, all co-resident on 152 SMs
#define KCHUNKS   16    // K split of the recurrent GEMM (64 each)

typedef unsigned long long ull;

// -------- scratch (device globals: no allocation allowed) --------
__device__ float g_xp[(size_t)Tv * Bv * Hv];        // [t][b][h]  512 MB
__device__ float g_h[2][Bv * Hv];                   // hidden state double buffer
__device__ float g_part[KCHUNKS][Bv * Hv];          // split-K partials (8 MB)
__device__ unsigned g_bar_count;                    // zero-initialized
__device__ volatile unsigned g_bar_gen;             // generation counter

// -------- packed f32x2 helpers (full-rate fp32 on sm_103a) --------
__device__ __forceinline__ void ffma2(ull& d, ull a, ull b) {
    asm("fma.rn.f32x2 %0, %1, %2, %0;" : "+l"(d) : "l"(a), "l"(b));
}
__device__ __forceinline__ ull pack2(float lo, float hi) {
    ull r; asm("mov.b64 %0, {%1, %2};" : "=l"(r) : "f"(lo), "f"(hi)); return r;
}
__device__ __forceinline__ float2 unpack2(ull v) {
    float2 r; asm("mov.b64 {%0, %1}, %2;" : "=f"(r.x), "=f"(r.y) : "l"(v)); return r;
}

// -------- grid-wide barrier (all threads fence: CCTL.IVALL flushes L1) --------
__device__ __forceinline__ void grid_bar() {
    __threadfence();              // make my stores visible + invalidate my L1
    __syncthreads();
    if (threadIdx.x == 0) {
        unsigned gen = g_bar_gen; // volatile read
        unsigned prev = atomicAdd(&g_bar_count, 1u);
        if (prev == NBLK_SCAN - 1) {
            g_bar_count = 0;
            __threadfence();
            g_bar_gen = gen + 1;  // release
        } else {
            while (g_bar_gen == gen) { __nanosleep(64); }
        }
    }
    __syncthreads();
}

// ============================================================
// Kernel A: xp[t][b][h] = x[b][t][:] @ kernel[:, h] + bias[h]
// M = B*T = 131072 (row m = b*T + t), K = I = 512, N = H = 1024
// 128x128 block tile, 8x8 thread tile, FFMA2 inner product
// ============================================================
__global__ void __launch_bounds__(256, 1) xp_gemm(
    const float* __restrict__ X, const float* __restrict__ WK,
    const float* __restrict__ bias)
{
    __shared__ float As[8][128];
    __shared__ float Bs[8][128];

    const int tid = threadIdx.x;
    const int tx = tid & 15;       // N direction (0..15)
    const int ty = tid >> 4;       // M direction (0..15)
    const int n0 = blockIdx.x * 128;
    const int m0 = blockIdx.y * 128;

    const int arow = tid >> 1;            // 0..127
    const int acol = (tid & 1) * 4;       // 0 or 4
    const int brow = tid >> 5;            // 0..7
    const int bcol = (tid & 31) * 4;      // 0..124

    ull acc[8][4];
#pragma unroll
    for (int i = 0; i < 8; i++)
#pragma unroll
        for (int j = 0; j < 4; j++) acc[i][j] = 0ull;

    const float* Aptr = X + (size_t)(m0 + arow) * Iv + acol;
    const float* Bptr = WK + (size_t)brow * Hv + n0 + bcol;

    for (int k0 = 0; k0 < Iv; k0 += 8) {
        float4 av = *(const float4*)(Aptr + k0);
        float4 bv = *(const float4*)(Bptr + (size_t)k0 * Hv);
        __syncthreads();
        As[acol + 0][arow] = av.x;
        As[acol + 1][arow] = av.y;
        As[acol + 2][arow] = av.z;
        As[acol + 3][arow] = av.w;
        *(float4*)&Bs[brow][bcol] = bv;
        __syncthreads();
#pragma unroll
        for (int kk = 0; kk < 8; kk++) {
            float4 a0 = *(const float4*)&As[kk][ty * 8];
            float4 a1 = *(const float4*)&As[kk][ty * 8 + 4];
            ull b0 = *(const ull*)&Bs[kk][tx * 8 + 0];
            ull b1 = *(const ull*)&Bs[kk][tx * 8 + 2];
            ull b2 = *(const ull*)&Bs[kk][tx * 8 + 4];
            ull b3 = *(const ull*)&Bs[kk][tx * 8 + 6];
            float af[8] = {a0.x, a0.y, a0.z, a0.w, a1.x, a1.y, a1.z, a1.w};
#pragma unroll
            for (int i = 0; i < 8; i++) {
                ull ap = pack2(af[i], af[i]);
                ffma2(acc[i][0], ap, b0);
                ffma2(acc[i][1], ap, b1);
                ffma2(acc[i][2], ap, b2);
                ffma2(acc[i][3], ap, b3);
            }
        }
    }

    float4 bb0 = *(const float4*)&bias[n0 + tx * 8];
    float4 bb1 = *(const float4*)&bias[n0 + tx * 8 + 4];

#pragma unroll
    for (int i = 0; i < 8; i++) {
        int m = m0 + ty * 8 + i;
        int bb = m >> 10;       // / T
        int tt = m & 1023;      // % T
        float* dst = g_xp + ((size_t)tt * Bv + bb) * Hv + n0 + tx * 8;
        float2 p0 = unpack2(acc[i][0]);
        float2 p1 = unpack2(acc[i][1]);
        float2 p2 = unpack2(acc[i][2]);
        float2 p3 = unpack2(acc[i][3]);
        float4 v0 = {p0.x + bb0.x, p0.y + bb0.y, p1.x + bb0.z, p1.y + bb0.w};
        float4 v1 = {p2.x + bb1.x, p2.y + bb1.y, p3.x + bb1.z, p3.y + bb1.w};
        *(float4*)(dst + 0) = v0;
        *(float4*)(dst + 4) = v1;
    }
}

// ============================================================
// Kernel B: persistent recurrent scan.
// 128 blocks; block = (kc, nt): phase1 partial GEMM
//   part[kc][0:128, nt*128:+128] = h[:, kc*64:+64] @ Wr[kc*64:+64, ntile]
// barrier; phase2: h_next = tanh(xp_t + sum_kc part[kc]); barrier.
// ============================================================
__global__ void __launch_bounds__(256, 1) scan_kernel(const float* __restrict__ WR)
{
    __shared__ float As[8][128];
    __shared__ float Bs[8][128];

    const int tid = threadIdx.x;
    const int tx = tid & 15;
    const int ty = tid >> 4;
    const int kc = blockIdx.x >> 3;       // 0..15
    const int nt = blockIdx.x & 7;        // 0..7
    const int kbase = kc * 64;
    const int nbase = nt * 128;

    const int arow = tid >> 1;
    const int acol = (tid & 1) * 4;
    const int brow = tid >> 5;
    const int bcol = (tid & 31) * 4;

    const int e = (blockIdx.x * 256 + tid) * 4;   // flat element [0, 131072)

    // zero initial hidden state
    {
        float4 z = {0.f, 0.f, 0.f, 0.f};
        *(float4*)&g_h[0][e] = z;
    }
    grid_bar();

    int cur = 0;
#pragma unroll 1
    for (int t = 0; t < Tv; t++) {
        const float* hcur = g_h[cur];

        // ---- phase 1: partial GEMM 128x128x64 ----
        ull acc[8][4];
#pragma unroll
        for (int i = 0; i < 8; i++)
#pragma unroll
            for (int j = 0; j < 4; j++) acc[i][j] = 0ull;

        const float* Aptr = hcur + (size_t)arow * Hv + kbase + acol;
        const float* Bptr = WR + (size_t)(kbase + brow) * Hv + nbase + bcol;

#pragma unroll 1
        for (int ko = 0; ko < 64; ko += 8) {
            float4 av = __ldcg((const float4*)(Aptr + ko));
            float4 bv = *(const float4*)(Bptr + (size_t)ko * Hv);
            __syncthreads();
            As[acol + 0][arow] = av.x;
            As[acol + 1][arow] = av.y;
            As[acol + 2][arow] = av.z;
            As[acol + 3][arow] = av.w;
            *(float4*)&Bs[brow][bcol] = bv;
            __syncthreads();
#pragma unroll
            for (int kk = 0; kk < 8; kk++) {
                float4 a0 = *(const float4*)&As[kk][ty * 8];
                float4 a1 = *(const float4*)&As[kk][ty * 8 + 4];
                ull b0 = *(const ull*)&Bs[kk][tx * 8 + 0];
                ull b1 = *(const ull*)&Bs[kk][tx * 8 + 2];
                ull b2 = *(const ull*)&Bs[kk][tx * 8 + 4];
                ull b3 = *(const ull*)&Bs[kk][tx * 8 + 6];
                float af[8] = {a0.x, a0.y, a0.z, a0.w, a1.x, a1.y, a1.z, a1.w};
#pragma unroll
                for (int i = 0; i < 8; i++) {
                    ull ap = pack2(af[i], af[i]);
                    ffma2(acc[i][0], ap, b0);
                    ffma2(acc[i][1], ap, b1);
                    ffma2(acc[i][2], ap, b2);
                    ffma2(acc[i][3], ap, b3);
                }
            }
        }

        {
            float* P = g_part[kc];
#pragma unroll
            for (int i = 0; i < 8; i++) {
                int row = ty * 8 + i;
                float2 p0 = unpack2(acc[i][0]);
                float2 p1 = unpack2(acc[i][1]);
                float2 p2 = unpack2(acc[i][2]);
                float2 p3 = unpack2(acc[i][3]);
                float4 v0 = {p0.x, p0.y, p1.x, p1.y};
                float4 v1 = {p2.x, p2.y, p3.x, p3.y};
                float* dst = P + (size_t)row * Hv + nbase + tx * 8;
                *(float4*)(dst + 0) = v0;
                *(float4*)(dst + 4) = v1;
            }
        }

        grid_bar();

        // ---- phase 2: reduce partials + xp + tanh -> h_next ----
        {
            float4 s = *(const float4*)&g_xp[(size_t)t * (Bv * Hv) + e];
#pragma unroll
            for (int c = 0; c < KCHUNKS; c++) {
                float4 p = __ldcg((const float4*)&g_part[c][e]);
                s.x += p.x; s.y += p.y; s.z += p.z; s.w += p.w;
            }
            float4 hn;
            hn.x = tanhf(s.x); hn.y = tanhf(s.y);
            hn.z = tanhf(s.z); hn.w = tanhf(s.w);
            *(float4*)&g_h[cur ^ 1][e] = hn;
        }

        grid_bar();
        cur ^= 1;
    }
    // T even -> final hidden state ends in g_h[0]
}

// ============================================================
// Kernel C: out[b][o] = h_last[b][:] @ fc_w[:, o] + fc_b[o]
// ============================================================
__global__ void __launch_bounds__(256, 1) fc_kernel(
    const float* __restrict__ fcw, const float* __restrict__ fcb,
    float* __restrict__ out)
{
    __shared__ float hs[Hv];
    const int b = blockIdx.x;
    const float* hrow = g_h[0] + (size_t)b * Hv;
    for (int i = threadIdx.x; i < Hv; i += 256) hs[i] = hrow[i];
    __syncthreads();

    const int o = threadIdx.x;   // 0..255 == Ov
    float acc = 0.f;
#pragma unroll 4
    for (int k = 0; k < Hv; k++) {
        acc = fmaf(hs[k], fcw[(size_t)k * Ov + o], acc);
    }
    out[(size_t)b * Ov + o] = acc + fcb[o];
}

// ============================================================
extern "C" void kernel_launch(void* const* d_in, const int* in_sizes, int n_in,
                              void* d_out, int out_size)
{
    const float* x   = (const float*)d_in[0];   // [B,T,I]
    const float* wk  = (const float*)d_in[1];   // [I,H]
    const float* wr  = (const float*)d_in[2];   // [H,H]
    const float* bs  = (const float*)d_in[3];   // [H]
    const float* fcw = (const float*)d_in[4];   // [H,O]
    const float* fcb = (const float*)d_in[5];   // [O]
    float* out = (float*)d_out;                 // [B,O]

    dim3 gA(Hv / 128, (Bv * Tv) / 128);         // (8, 1024)
    xp_gemm<<<gA, 256>>>(x, wk, bs);
    scan_kernel<<<NBLK_SCAN, 256>>>(wr);
    fc_kernel<<<Bv, 256>>>(fcw, fcb, out);
}

// round 2
// speedup vs baseline: 1.1590x; 1.1590x over previous
#include <cuda_runtime.h>
#include <cuda_bf16.h>
#include <math.h>

// Problem dims
#define Bv 128
#define Tv 1024
#define Iv 512
#define Hv 1024
#define Ov 256

#define NBLK_SCAN 128   // 16 k-chunks x 8 n-tiles
#define KCHUNKS   16    // K split of the recurrent GEMM (64 each)

typedef unsigned long long ull;

// -------- scratch (device globals: no allocation allowed) --------
__device__ float g_xp[(size_t)Tv * Bv * Hv];        // [t][b][h]  512 MB
__device__ float g_h[2][Bv * Hv];                   // hidden state double buffer
__device__ float g_part[KCHUNKS][Bv * Hv];          // split-K partials (8 MB)
__device__ unsigned g_bar_count;                    // zero-initialized
__device__ unsigned g_bar_gen;                      // generation counter (monotonic)

// -------- packed f32x2 helpers (full-rate fp32 on sm_103a) --------
__device__ __forceinline__ void ffma2(ull& d, ull a, ull b) {
    asm("fma.rn.f32x2 %0, %1, %2, %0;" : "+l"(d) : "l"(a), "l"(b));
}
__device__ __forceinline__ ull pack2(float lo, float hi) {
    ull r; asm("mov.b64 %0, {%1, %2};" : "=l"(r) : "f"(lo), "f"(hi)); return r;
}
__device__ __forceinline__ float2 unpack2(ull v) {
    float2 r; asm("mov.b64 {%0, %1}, %2;" : "=f"(r.x), "=f"(r.y) : "l"(v)); return r;
}

// -------- grid-wide barrier: 1-thread cumulative fence + acquire spin --------
__device__ __forceinline__ void grid_bar() {
    __syncthreads();
    if (threadIdx.x == 0) {
        unsigned gen;
        asm volatile("ld.relaxed.gpu.u32 %0, [%1];" : "=r"(gen) : "l"(&g_bar_gen));
        // cumulative fence: makes this CTA's prior stores (ordered to us by
        // __syncthreads) visible at gpu scope before the arrival is observed
        asm volatile("fence.acq_rel.gpu;" ::: "memory");
        unsigned prev;
        asm volatile("atom.relaxed.gpu.global.add.u32 %0, [%1], 1;"
                     : "=r"(prev) : "l"(&g_bar_count) : "memory");
        if (prev == NBLK_SCAN - 1) {
            asm volatile("st.relaxed.gpu.u32 [%0], 0;" :: "l"(&g_bar_count) : "memory");
            asm volatile("st.release.gpu.u32 [%0], %1;" :: "l"(&g_bar_gen), "r"(gen + 1) : "memory");
        } else {
            unsigned cur;
            do {
                asm volatile("ld.acquire.gpu.u32 %0, [%1];" : "=r"(cur) : "l"(&g_bar_gen) : "memory");
            } while (cur == gen);
        }
    }
    __syncthreads();
}

// ============================================================
// Kernel A: xp[t][b][h] = x[b][t][:] @ kernel[:, h] + bias[h]
// M = B*T = 131072 (row m = b*T + t), K = I = 512, N = H = 1024
// 128x128 block tile, 8x8 thread tile, FFMA2 inner product
// ============================================================
__global__ void __launch_bounds__(256, 2) xp_gemm(
    const float* __restrict__ X, const float* __restrict__ WK,
    const float* __restrict__ bias)
{
    __shared__ float As[8][128];
    __shared__ float Bs[8][128];

    const int tid = threadIdx.x;
    const int tx = tid & 15;       // N direction (0..15)
    const int ty = tid >> 4;       // M direction (0..15)
    const int n0 = blockIdx.x * 128;
    const int m0 = blockIdx.y * 128;

    const int arow = tid >> 1;            // 0..127
    const int acol = (tid & 1) * 4;       // 0 or 4
    const int brow = tid >> 5;            // 0..7
    const int bcol = (tid & 31) * 4;      // 0..124

    ull acc[8][4];
#pragma unroll
    for (int i = 0; i < 8; i++)
#pragma unroll
        for (int j = 0; j < 4; j++) acc[i][j] = 0ull;

    const float* Aptr = X + (size_t)(m0 + arow) * Iv + acol;
    const float* Bptr = WK + (size_t)brow * Hv + n0 + bcol;

    for (int k0 = 0; k0 < Iv; k0 += 8) {
        float4 av = *(const float4*)(Aptr + k0);
        float4 bv = *(const float4*)(Bptr + (size_t)k0 * Hv);
        __syncthreads();
        As[acol + 0][arow] = av.x;
        As[acol + 1][arow] = av.y;
        As[acol + 2][arow] = av.z;
        As[acol + 3][arow] = av.w;
        *(float4*)&Bs[brow][bcol] = bv;
        __syncthreads();
#pragma unroll
        for (int kk = 0; kk < 8; kk++) {
            float4 a0 = *(const float4*)&As[kk][ty * 8];
            float4 a1 = *(const float4*)&As[kk][ty * 8 + 4];
            ull b0 = *(const ull*)&Bs[kk][tx * 8 + 0];
            ull b1 = *(const ull*)&Bs[kk][tx * 8 + 2];
            ull b2 = *(const ull*)&Bs[kk][tx * 8 + 4];
            ull b3 = *(const ull*)&Bs[kk][tx * 8 + 6];
            float af[8] = {a0.x, a0.y, a0.z, a0.w, a1.x, a1.y, a1.z, a1.w};
#pragma unroll
            for (int i = 0; i < 8; i++) {
                ull ap = pack2(af[i], af[i]);
                ffma2(acc[i][0], ap, b0);
                ffma2(acc[i][1], ap, b1);
                ffma2(acc[i][2], ap, b2);
                ffma2(acc[i][3], ap, b3);
            }
        }
    }

    float4 bb0 = *(const float4*)&bias[n0 + tx * 8];
    float4 bb1 = *(const float4*)&bias[n0 + tx * 8 + 4];

#pragma unroll
    for (int i = 0; i < 8; i++) {
        int m = m0 + ty * 8 + i;
        int bb = m >> 10;       // / T
        int tt = m & 1023;      // % T
        float* dst = g_xp + ((size_t)tt * Bv + bb) * Hv + n0 + tx * 8;
        float2 p0 = unpack2(acc[i][0]);
        float2 p1 = unpack2(acc[i][1]);
        float2 p2 = unpack2(acc[i][2]);
        float2 p3 = unpack2(acc[i][3]);
        float4 v0 = {p0.x + bb0.x, p0.y + bb0.y, p1.x + bb0.z, p1.y + bb0.w};
        float4 v1 = {p2.x + bb1.x, p2.y + bb1.y, p3.x + bb1.z, p3.y + bb1.w};
        *(float4*)(dst + 0) = v0;
        *(float4*)(dst + 4) = v1;
    }
}

// ============================================================
// Kernel B: persistent recurrent scan, Wr resident in SMEM.
// 128 blocks; block = (kc, nt): phase1 partial GEMM
//   part[kc][0:128, nt*128:+128] = h[:, kc*64:+64] @ Wr[kc*64:+64, ntile]
// barrier; phase2: h_next = tanh(xp_t + sum_kc part[kc]); barrier.
// Dynamic SMEM: Ws[64][128] (Wr slice, loaded once) + As[64][128] (h slice)
// ============================================================
__global__ void __launch_bounds__(256, 1) scan_kernel(const float* __restrict__ WR)
{
    extern __shared__ float smem_dyn[];
    float* Ws = smem_dyn;            // [64][128] = 8192 floats
    float* As = smem_dyn + 8192;     // [64][128] = 8192 floats

    const int tid = threadIdx.x;
    const int tx = tid & 15;
    const int ty = tid >> 4;
    const int kc = blockIdx.x >> 3;       // 0..15
    const int nt = blockIdx.x & 7;        // 0..7
    const int kbase = kc * 64;
    const int nbase = nt * 128;

    const int arow = tid >> 1;            // 0..127
    const int acol = (tid & 1) * 4;       // 0 or 4
    const int brow = tid >> 5;            // 0..7
    const int bcol = (tid & 31) * 4;      // 0..124

    const int e = (blockIdx.x * 256 + tid) * 4;   // flat element [0, 131072)

    // ---- load resident Wr slice: Ws[k][n] = WR[kbase+k][nbase+n] ----
#pragma unroll
    for (int c = 0; c < 8; c++) {
        int k = c * 8 + brow;
        float4 v = *(const float4*)(WR + (size_t)(kbase + k) * Hv + nbase + bcol);
        *(float4*)&Ws[k * 128 + bcol] = v;
    }

    // zero initial hidden state
    {
        float4 z = {0.f, 0.f, 0.f, 0.f};
        *(float4*)&g_h[0][e] = z;
    }
    grid_bar();

    int cur = 0;
#pragma unroll 1
    for (int t = 0; t < Tv; t++) {
        const float* hcur = g_h[cur];

        // prefetch xp[t] slice (independent of barriers / h)
        float4 xpv = *(const float4*)&g_xp[(size_t)t * (Bv * Hv) + e];

        // ---- stage h slice (transposed): As[k][row] ----
#pragma unroll
        for (int c = 0; c < 8; c++) {
            int k = c * 8 + acol;
            float4 av = __ldcg((const float4*)(hcur + (size_t)arow * Hv + kbase + c * 8 + acol));
            As[(k + 0) * 128 + arow] = av.x;
            As[(k + 1) * 128 + arow] = av.y;
            As[(k + 2) * 128 + arow] = av.z;
            As[(k + 3) * 128 + arow] = av.w;
        }
        __syncthreads();

        // ---- phase 1: partial GEMM 128x128x64 from SMEM ----
        ull acc[8][4];
#pragma unroll
        for (int i = 0; i < 8; i++)
#pragma unroll
            for (int j = 0; j < 4; j++) acc[i][j] = 0ull;

#pragma unroll 8
        for (int kk = 0; kk < 64; kk++) {
            float4 a0 = *(const float4*)&As[kk * 128 + ty * 8];
            float4 a1 = *(const float4*)&As[kk * 128 + ty * 8 + 4];
            ull b0 = *(const ull*)&Ws[kk * 128 + tx * 8 + 0];
            ull b1 = *(const ull*)&Ws[kk * 128 + tx * 8 + 2];
            ull b2 = *(const ull*)&Ws[kk * 128 + tx * 8 + 4];
            ull b3 = *(const ull*)&Ws[kk * 128 + tx * 8 + 6];
            float af[8] = {a0.x, a0.y, a0.z, a0.w, a1.x, a1.y, a1.z, a1.w};
#pragma unroll
            for (int i = 0; i < 8; i++) {
                ull ap = pack2(af[i], af[i]);
                ffma2(acc[i][0], ap, b0);
                ffma2(acc[i][1], ap, b1);
                ffma2(acc[i][2], ap, b2);
                ffma2(acc[i][3], ap, b3);
            }
        }

        // ---- write split-K partials ----
        {
            float* P = g_part[kc];
#pragma unroll
            for (int i = 0; i < 8; i++) {
                int row = ty * 8 + i;
                float2 p0 = unpack2(acc[i][0]);
                float2 p1 = unpack2(acc[i][1]);
                float2 p2 = unpack2(acc[i][2]);
                float2 p3 = unpack2(acc[i][3]);
                float4 v0 = {p0.x, p0.y, p1.x, p1.y};
                float4 v1 = {p2.x, p2.y, p3.x, p3.y};
                float* dst = P + (size_t)row * Hv + nbase + tx * 8;
                *(float4*)(dst + 0) = v0;
                *(float4*)(dst + 4) = v1;
            }
        }

        grid_bar();

        // ---- phase 2: reduce partials + xp + tanh -> h_next ----
        {
            float4 s = xpv;
#pragma unroll
            for (int c = 0; c < KCHUNKS; c++) {
                float4 p = __ldcg((const float4*)&g_part[c][e]);
                s.x += p.x; s.y += p.y; s.z += p.z; s.w += p.w;
            }
            float4 hn;
            hn.x = tanhf(s.x); hn.y = tanhf(s.y);
            hn.z = tanhf(s.z); hn.w = tanhf(s.w);
            *(float4*)&g_h[cur ^ 1][e] = hn;
        }

        grid_bar();
        cur ^= 1;
    }
    // T even -> final hidden state ends in g_h[0]
}

// ============================================================
// Kernel C: out[b][o] = h_last[b][:] @ fc_w[:, o] + fc_b[o]
// ============================================================
__global__ void __launch_bounds__(256, 1) fc_kernel(
    const float* __restrict__ fcw, const float* __restrict__ fcb,
    float* __restrict__ out)
{
    __shared__ float hs[Hv];
    const int b = blockIdx.x;
    const float* hrow = g_h[0] + (size_t)b * Hv;
    for (int i = threadIdx.x; i < Hv; i += 256) hs[i] = hrow[i];
    __syncthreads();

    const int o = threadIdx.x;   // 0..255 == Ov
    float acc = 0.f;
#pragma unroll 4
    for (int k = 0; k < Hv; k++) {
        acc = fmaf(hs[k], fcw[(size_t)k * Ov + o], acc);
    }
    out[(size_t)b * Ov + o] = acc + fcb[o];
}

// ============================================================
extern "C" void kernel_launch(void* const* d_in, const int* in_sizes, int n_in,
                              void* d_out, int out_size)
{
    const float* x   = (const float*)d_in[0];   // [B,T,I]
    const float* wk  = (const float*)d_in[1];   // [I,H]
    const float* wr  = (const float*)d_in[2];   // [H,H]
    const float* bs  = (const float*)d_in[3];   // [H]
    const float* fcw = (const float*)d_in[4];   // [H,O]
    const float* fcb = (const float*)d_in[5];   // [O]
    float* out = (float*)d_out;                 // [B,O]

    static int smem_set = 0;
    if (!smem_set) {
        cudaFuncSetAttribute(scan_kernel,
                             cudaFuncAttributeMaxDynamicSharedMemorySize, 65536);
        smem_set = 1;
    }

    dim3 gA(Hv / 128, (Bv * Tv) / 128);         // (8, 1024)
    xp_gemm<<<gA, 256>>>(x, wk, bs);
    scan_kernel<<<NBLK_SCAN, 256, 65536>>>(wr);
    fc_kernel<<<Bv, 256>>>(fcw, fcb, out);
}